// round 2
// baseline (speedup 1.0000x reference)
#include <cuda_runtime.h>
#include <cstdint>

#define ML   80        // MAXLEN
#define LD   10        // LATENT
#define BSZ  512       // BATCH
#define HID  32        // HIDDEN
#define ST   10        // STEPS
#define NKEYS 880      // ML*(ST+1)
#define NPER 5120      // BSZ*LD

// Scratch (device globals — no allocation allowed)
__device__ uint2 g_keys[NKEYS];
__device__ float g_noise[NKEYS * NPER];          // 18.0 MB: pre-sampled normals
__device__ float g_acc[BSZ * ML * HID];          // 5.2 MB: exclusive prefix of z@W1

// ---------------- threefry2x32-20 (exact JAX semantics) ----------------
__device__ __forceinline__ uint32_t rotl32(uint32_t x, int r) {
    return __funnelshift_l(x, x, r);
}

__device__ __forceinline__ void threefry2x32(uint32_t k1, uint32_t k2,
                                             uint32_t &x0, uint32_t &x1) {
    uint32_t k3 = k1 ^ k2 ^ 0x1BD11BDAu;
    x0 += k1; x1 += k2;
#define R1(r) { x0 += x1; x1 = rotl32(x1, r); x1 ^= x0; }
#define RA R1(13) R1(15) R1(26) R1(6)
#define RB R1(17) R1(29) R1(16) R1(24)
    RA  x0 += k2; x1 += k3 + 1u;
    RB  x0 += k3; x1 += k1 + 2u;
    RA  x0 += k1; x1 += k2 + 3u;
    RB  x0 += k2; x1 += k3 + 4u;
    RA  x0 += k3; x1 += k1 + 5u;
#undef R1
#undef RA
#undef RB
}

// bits -> uniform(lo=nextafter(-1,0), 1) -> sqrt(2)*erfinv  (matches jax.random.normal)
__device__ __forceinline__ float bits_to_normal(uint32_t bits) {
    const float lo = __uint_as_float(0xBF7FFFFFu);       // nextafterf(-1, 0)
    float f = __fsub_rn(__uint_as_float((bits >> 9) | 0x3F800000u), 1.0f); // [0,1)
    float span = __fsub_rn(1.0f, lo);                    // = 2.0f after f32 rounding
    float u = __fadd_rn(__fmul_rn(f, span), lo);
    u = fmaxf(u, lo);
    return __fmul_rn(1.41421356237309515f, erfinvf(u));
}

// ---- kernel 1: partitionable split of root key (0,1337) into 880 keys ----
// key_j = threefry2x32(root, counter=(0, j)); output pair IS the new key.
__global__ void k_keys() {
    int j = blockIdx.x * blockDim.x + threadIdx.x;
    if (j >= NKEYS) return;
    uint32_t x0 = 0u, x1 = (uint32_t)j;
    threefry2x32(0u, 1337u, x0, x1);
    g_keys[j] = make_uint2(x0, x1);
}

// ---- kernel 2: partitionable random_bits(32): bits[m] = o1^o2 of counter (0, m) ----
__global__ void k_noise() {
    int idx = blockIdx.x * blockDim.x + threadIdx.x;   // [0, NKEYS*NPER)
    int j = idx / NPER;
    int m = idx - j * NPER;
    uint2 k = g_keys[j];
    uint32_t x0 = 0u, x1 = (uint32_t)m;
    threefry2x32(k.x, k.y, x0, x1);
    g_noise[idx] = bits_to_normal(x0 ^ x1);
}

// ---------------- kernel 3: P[b,l,j] = sum_d z[b,l,d] * W1[l*10+d, j] ----------------
__global__ void k_pref(const float* __restrict__ z_mean, const float* __restrict__ W1) {
    int gt = blockIdx.x * blockDim.x + threadIdx.x;
    int wt = gt >> 5;                  // (b,l) task, one warp each; 40960 total
    int lane = gt & 31;                // hidden unit j
    int b = wt / ML;
    int l = wt - b * ML;
    float p = 0.f;
#pragma unroll
    for (int d = 0; d < LD; d++)
        p = fmaf(z_mean[(b * ML + l) * LD + d], W1[(l * LD + d) * HID + lane], p);
    g_acc[wt * HID + lane] = p;
}

// ---------------- kernel 4: exclusive prefix over l, per (b, j) ----------------
__global__ void k_scan() {
    int b = blockIdx.x;        // 512 blocks
    int j = threadIdx.x;       // 32 threads
    float run = 0.f;
    for (int l = 0; l < ML; l++) {
        int idx = (b * ML + l) * HID + j;
        float v = g_acc[idx];
        g_acc[idx] = run;
        run += v;
    }
}

// ---------------- kernel 5: main diffusion simulation, 1 warp per (i, b) ----------------
__global__ void __launch_bounds__(256) k_main(
    const float* __restrict__ z_mean, const float* __restrict__ z_log_var,
    const float* __restrict__ W1, const float* __restrict__ b1,
    const float* __restrict__ W2, const float* __restrict__ b2,
    float* __restrict__ out)
{
    __shared__ float s_xt[8][LD];
    __shared__ float s_rh[8][HID];
    int w = threadIdx.x >> 5;
    int lane = threadIdx.x & 31;
    int task = blockIdx.x * 8 + w;     // 40960 tasks exactly
    int i = task >> 9;                 // chain index (0..79)
    int b = task & 511;                // batch index
    int dl = (lane < LD) ? lane : 0;   // latent lane (lanes >=10 shadow d=0)

    // per-hidden-unit constants (lane = j)
    float acc = g_acc[(b * ML + i) * HID + lane];   // prefix contribution (l < i)
    float w1i[LD];
#pragma unroll
    for (int d = 0; d < LD; d++) w1i[d] = W1[(i * LD + d) * HID + lane];
    float w1t = W1[800 * HID + lane];
    float b1v = b1[lane];

    // per-latent-dim constants (dl = d)
    float w2r[HID];
#pragma unroll
    for (int j = 0; j < HID; j++) w2r[j] = W2[j * LD + dl];
    float b2v = b2[dl];

    int zi = (b * ML + i) * LD + dl;
    float mu   = z_mean[zi];
    float sig  = expf(z_log_var[zi]);
    float sstd = sqrtf(sig);

    const float* nb = g_noise + (size_t)(i * 11) * NPER + b * LD;
    float xt = mu + sstd * nb[dl];                  // x0
    float err = 0.f;
    const float sqdt = sqrtf(0.1f);

    if (lane < LD) s_xt[w][lane] = xt;
    __syncwarp();

#pragma unroll
    for (int s = 0; s < ST; s++) {
        float t = (float)i + (float)s * 0.1f;
        float h = acc + b1v + t * w1t;
#pragma unroll
        for (int d = 0; d < LD; d++) h = fmaf(s_xt[w][d], w1i[d], h);
        float rh = fmaxf(h, 0.f);
        s_rh[w][lane] = rh;
        __syncwarp();

        float sc = b2v;
#pragma unroll
        for (int j = 0; j < HID; j++) sc = fmaf(s_rh[w][j], w2r[j], sc);

        err += fabsf((mu - xt) / sstd - sc);
        float nv = nb[(1 + s) * NPER + dl];
        xt = xt + (0.5f * (sstd * sstd)) * sc + sstd * (nv * sqdt);
        if (lane < LD) s_xt[w][lane] = xt;
        __syncwarp();
    }

    if (lane < LD) {
        int o = (b * ML + i) * LD + lane;
        out[o] = xt;                        // sequence
        out[BSZ * ML * LD + o] = err;       // score_error
    }
}

// ---------------- launch ----------------
extern "C" void kernel_launch(void* const* d_in, const int* in_sizes, int n_in,
                              void* d_out, int out_size) {
    const float* z_mean    = (const float*)d_in[0];
    const float* z_log_var = (const float*)d_in[1];
    const float* W1        = (const float*)d_in[2];
    const float* b1        = (const float*)d_in[3];
    const float* W2        = (const float*)d_in[4];
    const float* b2        = (const float*)d_in[5];
    float* out = (float*)d_out;

    k_keys<<<4, 256>>>();
    k_noise<<<(NKEYS * NPER) / 256, 256>>>();            // 17600 blocks
    k_pref<<<(BSZ * ML * 32) / 256, 256>>>(z_mean, W1);  // 5120 blocks
    k_scan<<<BSZ, 32>>>();
    k_main<<<(BSZ * ML) / 8, 256>>>(z_mean, z_log_var, W1, b1, W2, b2, out);
}

// round 3
// speedup vs baseline: 1.7360x; 1.7360x over previous
#include <cuda_runtime.h>
#include <cstdint>

#define ML   80
#define LD   10
#define BSZ  512
#define HID  32
#define ST   10
#define NKEYS 880        // ML*(ST+1)
#define NPER 5120        // BSZ*LD
#define GPI  171         // task-groups (of 3 batches) per chain i: ceil(512/3)

__device__ float g_noise[NKEYS * NPER];   // 18.0 MB pre-sampled normals
__device__ float g_acc[BSZ * ML * HID];   // 5.2 MB exclusive prefix of z@W1

// ---------------- threefry2x32-20 ----------------
__device__ __forceinline__ uint32_t rotl32(uint32_t x, int r) {
    return __funnelshift_l(x, x, r);
}
__device__ __forceinline__ void threefry2x32(uint32_t k1, uint32_t k2,
                                             uint32_t &x0, uint32_t &x1) {
    uint32_t k3 = k1 ^ k2 ^ 0x1BD11BDAu;
    x0 += k1; x1 += k2;
#define R1(r) { x0 += x1; x1 = rotl32(x1, r); x1 ^= x0; }
#define RA R1(13) R1(15) R1(26) R1(6)
#define RB R1(17) R1(29) R1(16) R1(24)
    RA  x0 += k2; x1 += k3 + 1u;
    RB  x0 += k3; x1 += k1 + 2u;
    RA  x0 += k1; x1 += k2 + 3u;
    RB  x0 += k2; x1 += k3 + 4u;
    RA  x0 += k3; x1 += k1 + 5u;
#undef R1
#undef RA
#undef RB
}

__device__ __forceinline__ float bits_to_normal(uint32_t bits) {
    const float lo = __uint_as_float(0xBF7FFFFFu);       // nextafterf(-1, 0)
    float f = __fsub_rn(__uint_as_float((bits >> 9) | 0x3F800000u), 1.0f);
    float span = __fsub_rn(1.0f, lo);                    // == 2.0f
    float u = __fadd_rn(__fmul_rn(f, span), lo);
    u = fmaxf(u, lo);
    return __fmul_rn(1.41421356237309515f, erfinvf(u));
}

// ---------------- k_init: blocks [0,512) prefix-scan, [512,18112) noise ----------------
__global__ void __launch_bounds__(256) k_init(const float* __restrict__ z_mean,
                                              const float* __restrict__ W1) {
    __shared__ float smem[800 + ML * HID];   // zb[800] | sp[80*32]
    int tid = threadIdx.x;

    if (blockIdx.x < BSZ) {
        // ===== prefix-scan branch: one block per batch b =====
        int b = blockIdx.x;
        float* zb = smem;            // 800
        float* sp = smem + 800;      // 2560

        // load z_mean[b] (800 floats)
#pragma unroll
        for (int r = 0; r < 4; r++) {
            int p = tid + 256 * r;
            if (p < ML * LD) zb[p] = z_mean[b * ML * LD + p];
        }
        __syncthreads();

        // P[l][j] = sum_d zb[l*10+d] * W1[(l*10+d)*32 + j]
#pragma unroll
        for (int r = 0; r < 10; r++) {
            int p = tid + 256 * r;               // 2560 elements
            int l = p >> 5, j = p & 31;
            float acc = 0.f;
#pragma unroll
            for (int d = 0; d < LD; d++)
                acc = fmaf(zb[l * LD + d], W1[(l * LD + d) * HID + j], acc);
            sp[p] = acc;
        }
        __syncthreads();

        // Hillis-Steele inclusive scan over l (stride 32 floats per l)
#pragma unroll
        for (int off = 1; off < ML; off <<= 1) {
            float v[10];
#pragma unroll
            for (int r = 0; r < 10; r++) {
                int p = tid + 256 * r;
                int l = p >> 5;
                v[r] = sp[p] + ((l >= off) ? sp[p - off * HID] : 0.f);
            }
            __syncthreads();
#pragma unroll
            for (int r = 0; r < 10; r++) sp[tid + 256 * r] = v[r];
            __syncthreads();
        }

        // exclusive shift -> g_acc[b][l][j]
#pragma unroll
        for (int r = 0; r < 10; r++) {
            int p = tid + 256 * r;
            int l = p >> 5;
            g_acc[b * ML * HID + p] = (l == 0) ? 0.f : sp[p - HID];
        }
    } else {
        // ===== noise branch: 20 blocks per key j =====
        int nb = blockIdx.x - BSZ;
        int j = nb / 20;
        int m = (nb - j * 20) * 256 + tid;
        __shared__ uint2 skey;
        if (tid == 0) {
            uint32_t x0 = 0u, x1 = (uint32_t)j;   // partitionable split of key(1337)
            threefry2x32(0u, 1337u, x0, x1);
            skey = make_uint2(x0, x1);
        }
        __syncthreads();
        uint32_t x0 = 0u, x1 = (uint32_t)m;       // partitionable random_bits
        threefry2x32(skey.x, skey.y, x0, x1);
        g_noise[j * NPER + m] = bits_to_normal(x0 ^ x1);
    }
}

// ---------------- k_main: one warp per (i, 3-batch group) ----------------
__global__ void __launch_bounds__(256) k_main(
    const float* __restrict__ z_mean, const float* __restrict__ z_log_var,
    const float* __restrict__ W1, const float* __restrict__ b1,
    const float* __restrict__ W2, const float* __restrict__ b2,
    float* __restrict__ out)
{
    __shared__ float s_xt[8][3][LD];
    __shared__ float s_rh[8][3][HID];
    int w = threadIdx.x >> 5;
    int lane = threadIdx.x & 31;
    int gw = blockIdx.x * 8 + w;       // 13680 warps exactly (80*171)
    int i = gw / GPI;
    int g = gw - i * GPI;
    int bs = 3 * g;

    // ---- j-role constants (lane = hidden unit j) ----
    float w1i[LD];
#pragma unroll
    for (int d = 0; d < LD; d++) w1i[d] = W1[(i * LD + d) * HID + lane];
    float w1t = W1[800 * HID + lane];
    float b1v = b1[lane];
    float accb[3];
#pragma unroll
    for (int k = 0; k < 3; k++) {
        int bk = min(bs + k, BSZ - 1);
        accb[k] = g_acc[(bk * ML + i) * HID + lane] + b1v;
    }

    // ---- (k,d)-role constants (lane -> task k, latent dim d) ----
    int kk = lane / LD;                      // 0..3 (lanes 30,31 -> 3)
    int d  = lane - kk * LD;
    int kc = min(kk, 2);
    bool kval = (kk < 3) && (bs + kk < BSZ);
    int bk2 = min(bs + kc, BSZ - 1);
    int zi = (bk2 * ML + i) * LD + d;

    float mu   = z_mean[zi];
    float sig  = expf(z_log_var[zi]);
    float sstd = sqrtf(sig);
    float b2v  = b2[d];
    float w2c[HID];
#pragma unroll
    for (int j = 0; j < HID; j++) w2c[j] = W2[j * LD + d];

    const float* nb = g_noise + (size_t)(i * 11) * NPER + bk2 * LD + d;
    float xt  = mu + sstd * nb[0];
    float err = 0.f;
    float halfsig = 0.5f * sig;
    float ssdt = sstd * 0.31622776601683794f;   // sstd * sqrt(DT)

    if (lane < 3 * LD) s_xt[w][kk][d] = xt;
    __syncwarp();

#pragma unroll
    for (int s = 0; s < ST; s++) {
        float t = (float)i + (float)s * 0.1f;
        // h-phase: lane = j, 3 tasks
#pragma unroll
        for (int k = 0; k < 3; k++) {
            float h = fmaf(t, w1t, accb[k]);
#pragma unroll
            for (int d2 = 0; d2 < LD; d2++) h = fmaf(s_xt[w][k][d2], w1i[d2], h);
            s_rh[w][k][lane] = fmaxf(h, 0.f);
        }
        __syncwarp();
        // sc-phase: lane = (k,d)
        const float4* rp = (const float4*)s_rh[w][kc];
        float sc = b2v;
#pragma unroll
        for (int q = 0; q < 8; q++) {
            float4 v = rp[q];
            sc = fmaf(v.x, w2c[4 * q + 0], sc);
            sc = fmaf(v.y, w2c[4 * q + 1], sc);
            sc = fmaf(v.z, w2c[4 * q + 2], sc);
            sc = fmaf(v.w, w2c[4 * q + 3], sc);
        }
        err += fabsf((mu - xt) / sstd - sc);
        xt = fmaf(halfsig, sc, xt) + ssdt * nb[(1 + s) * NPER];
        if (lane < 3 * LD) s_xt[w][kk][d] = xt;
        __syncwarp();
    }

    if (kval) {
        out[zi] = xt;                         // sequence
        out[BSZ * ML * LD + zi] = err;        // score_error
    }
}

// ---------------- launch ----------------
extern "C" void kernel_launch(void* const* d_in, const int* in_sizes, int n_in,
                              void* d_out, int out_size) {
    const float* z_mean    = (const float*)d_in[0];
    const float* z_log_var = (const float*)d_in[1];
    const float* W1        = (const float*)d_in[2];
    const float* b1        = (const float*)d_in[3];
    const float* W2        = (const float*)d_in[4];
    const float* b2        = (const float*)d_in[5];
    float* out = (float*)d_out;

    k_init<<<BSZ + NKEYS * 20, 256>>>(z_mean, W1);            // 18112 blocks
    k_main<<<(ML * GPI) / 8, 256>>>(z_mean, z_log_var, W1, b1, W2, b2, out);  // 1710 blocks
}

// round 4
// speedup vs baseline: 2.1327x; 1.2285x over previous
#include <cuda_runtime.h>
#include <cstdint>

#define ML   80
#define LD   10
#define BSZ  512
#define HID  32
#define ST   10
#define NKEYS 880        // ML*(ST+1)
#define GPI  171         // 3-batch groups per chain i: ceil(512/3)

__device__ uint2 g_keys[NKEYS];           // partitionable-split subkeys
__device__ float g_acc[BSZ * ML * HID];   // 5.2 MB exclusive prefix of z@W1

// ---------------- threefry2x32-20 ----------------
__device__ __forceinline__ uint32_t rotl32(uint32_t x, int r) {
    return __funnelshift_l(x, x, r);
}
__device__ __forceinline__ void threefry2x32(uint32_t k1, uint32_t k2,
                                             uint32_t &x0, uint32_t &x1) {
    uint32_t k3 = k1 ^ k2 ^ 0x1BD11BDAu;
    x0 += k1; x1 += k2;
#define R1(r) { x0 += x1; x1 = rotl32(x1, r); x1 ^= x0; }
#define RA R1(13) R1(15) R1(26) R1(6)
#define RB R1(17) R1(29) R1(16) R1(24)
    RA  x0 += k2; x1 += k3 + 1u;
    RB  x0 += k3; x1 += k1 + 2u;
    RA  x0 += k1; x1 += k2 + 3u;
    RB  x0 += k2; x1 += k3 + 4u;
    RA  x0 += k3; x1 += k1 + 5u;
#undef R1
#undef RA
#undef RB
}

__device__ __forceinline__ float bits_to_normal(uint32_t bits) {
    const float lo = __uint_as_float(0xBF7FFFFFu);       // nextafterf(-1, 0)
    float f = __fsub_rn(__uint_as_float((bits >> 9) | 0x3F800000u), 1.0f);
    float span = __fsub_rn(1.0f, lo);                    // == 2.0f
    float u = __fadd_rn(__fmul_rn(f, span), lo);
    u = fmaxf(u, lo);
    return __fmul_rn(1.41421356237309515f, erfinvf(u));
}

// ---------------- k_init: blocks [0,512) prefix-scan, [512,516) key table ----------------
__global__ void __launch_bounds__(256) k_init(const float* __restrict__ z_mean,
                                              const float* __restrict__ W1) {
    int tid = threadIdx.x;

    if (blockIdx.x >= BSZ) {
        int j = (blockIdx.x - BSZ) * 256 + tid;
        if (j < NKEYS) {
            uint32_t x0 = 0u, x1 = (uint32_t)j;   // partitionable split of key(1337)
            threefry2x32(0u, 1337u, x0, x1);
            g_keys[j] = make_uint2(x0, x1);
        }
        return;
    }

    // ===== prefix-scan branch: one block per batch b =====
    __shared__ float smem[800 + ML * HID];   // zb[800] | sp[80*32]
    int b = blockIdx.x;
    float* zb = smem;
    float* sp = smem + 800;

#pragma unroll
    for (int r = 0; r < 4; r++) {
        int p = tid + 256 * r;
        if (p < ML * LD) zb[p] = z_mean[b * ML * LD + p];
    }
    __syncthreads();

#pragma unroll
    for (int r = 0; r < 10; r++) {
        int p = tid + 256 * r;               // 2560 elements
        int l = p >> 5, j = p & 31;
        float a0 = 0.f, a1 = 0.f;
#pragma unroll
        for (int d = 0; d < LD; d += 2) {
            a0 = fmaf(zb[l * LD + d],     W1[(l * LD + d) * HID + j],     a0);
            a1 = fmaf(zb[l * LD + d + 1], W1[(l * LD + d + 1) * HID + j], a1);
        }
        sp[p] = a0 + a1;
    }
    __syncthreads();

#pragma unroll
    for (int off = 1; off < ML; off <<= 1) {
        float v[10];
#pragma unroll
        for (int r = 0; r < 10; r++) {
            int p = tid + 256 * r;
            int l = p >> 5;
            v[r] = sp[p] + ((l >= off) ? sp[p - off * HID] : 0.f);
        }
        __syncthreads();
#pragma unroll
        for (int r = 0; r < 10; r++) sp[tid + 256 * r] = v[r];
        __syncthreads();
    }

#pragma unroll
    for (int r = 0; r < 10; r++) {
        int p = tid + 256 * r;
        int l = p >> 5;
        g_acc[b * ML * HID + p] = (l == 0) ? 0.f : sp[p - HID];
    }
}

// ---------------- k_main: fused noise + sim, one warp per (i, 3-batch group) ----------------
__global__ void __launch_bounds__(256) k_main(
    const float* __restrict__ z_mean, const float* __restrict__ z_log_var,
    const float* __restrict__ W1, const float* __restrict__ b1,
    const float* __restrict__ W2, const float* __restrict__ b2,
    float* __restrict__ out)
{
    __shared__ float s_xt[8][3][LD];
    __shared__ float s_rh[8][3][HID];
    int w = threadIdx.x >> 5;
    int lane = threadIdx.x & 31;
    int gw = blockIdx.x * 8 + w;       // 13680 warps exactly (80*171)
    int i = gw / GPI;
    int g = gw - i * GPI;
    int bs = 3 * g;

    // ---- (k,d)-role indices (lane -> task k, latent dim d) ----
    int kk = lane / LD;                      // 0..3 (lanes 30,31 -> 3)
    int d  = lane - kk * LD;
    int kc = min(kk, 2);
    bool kval = (kk < 3) && (bs + kk < BSZ);
    int bk2 = min(bs + kc, BSZ - 1);
    int zi = (bk2 * ML + i) * LD + d;

    // ---- inline noise: 11 normals per lane (keys i*11 .. i*11+10) ----
    float nrm[ST + 1];
    {
        uint32_t m = (uint32_t)(bk2 * LD + d);
        const uint2* kp = g_keys + i * 11;
#pragma unroll
        for (int s = 0; s <= ST; s++) {
            uint2 key = kp[s];
            uint32_t x0 = 0u, x1 = m;
            threefry2x32(key.x, key.y, x0, x1);
            nrm[s] = bits_to_normal(x0 ^ x1);
        }
    }

    // ---- j-role constants (lane = hidden unit j) ----
    float w1i[LD];
#pragma unroll
    for (int dd = 0; dd < LD; dd++) w1i[dd] = W1[(i * LD + dd) * HID + lane];
    float w1t = W1[800 * HID + lane];
    float b1v = b1[lane];
    float accb[3];
#pragma unroll
    for (int k = 0; k < 3; k++) {
        int bk = min(bs + k, BSZ - 1);
        accb[k] = g_acc[(bk * ML + i) * HID + lane] + b1v;
    }

    // ---- (k,d)-role constants ----
    float mu   = z_mean[zi];
    float sig  = expf(z_log_var[zi]);
    float sstd = sqrtf(sig);
    float b2v  = b2[d];
    float w2c[HID];
#pragma unroll
    for (int j = 0; j < HID; j++) w2c[j] = W2[j * LD + d];

    float xt  = mu + sstd * nrm[0];
    float err = 0.f;
    float halfsig = 0.5f * sig;
    float ssdt = sstd * 0.31622776601683794f;   // sstd * sqrt(DT)
    float rstd = 1.0f / sstd;

    if (lane < 3 * LD) s_xt[w][kk][d] = xt;
    __syncwarp();

#pragma unroll
    for (int s = 0; s < ST; s++) {
        float t = (float)i + (float)s * 0.1f;
        // h-phase: lane = j, 3 tasks, 2 parallel accumulators
#pragma unroll
        for (int k = 0; k < 3; k++) {
            float h0 = fmaf(t, w1t, accb[k]);
            float h1 = 0.f;
#pragma unroll
            for (int d2 = 0; d2 < LD; d2 += 2) {
                h0 = fmaf(s_xt[w][k][d2],     w1i[d2],     h0);
                h1 = fmaf(s_xt[w][k][d2 + 1], w1i[d2 + 1], h1);
            }
            s_rh[w][k][lane] = fmaxf(h0 + h1, 0.f);
        }
        __syncwarp();
        // sc-phase: lane = (k,d), 4 parallel accumulators
        const float4* rp = (const float4*)s_rh[w][kc];
        float sc0 = b2v, sc1 = 0.f, sc2 = 0.f, sc3 = 0.f;
#pragma unroll
        for (int q = 0; q < 8; q++) {
            float4 v = rp[q];
            sc0 = fmaf(v.x, w2c[4 * q + 0], sc0);
            sc1 = fmaf(v.y, w2c[4 * q + 1], sc1);
            sc2 = fmaf(v.z, w2c[4 * q + 2], sc2);
            sc3 = fmaf(v.w, w2c[4 * q + 3], sc3);
        }
        float sc = (sc0 + sc1) + (sc2 + sc3);
        err += fabsf((mu - xt) * rstd - sc);
        xt = fmaf(halfsig, sc, xt) + ssdt * nrm[1 + s];
        if (lane < 3 * LD) s_xt[w][kk][d] = xt;
        __syncwarp();
    }

    if (kval) {
        out[zi] = xt;                         // sequence
        out[BSZ * ML * LD + zi] = err;        // score_error
    }
}

// ---------------- launch ----------------
extern "C" void kernel_launch(void* const* d_in, const int* in_sizes, int n_in,
                              void* d_out, int out_size) {
    const float* z_mean    = (const float*)d_in[0];
    const float* z_log_var = (const float*)d_in[1];
    const float* W1        = (const float*)d_in[2];
    const float* b1        = (const float*)d_in[3];
    const float* W2        = (const float*)d_in[4];
    const float* b2        = (const float*)d_in[5];
    float* out = (float*)d_out;

    k_init<<<BSZ + 4, 256>>>(z_mean, W1);                                     // 516 blocks
    k_main<<<(ML * GPI) / 8, 256>>>(z_mean, z_log_var, W1, b1, W2, b2, out);  // 1710 blocks
}